// round 3
// baseline (speedup 1.0000x reference)
#include <cuda_runtime.h>
#include <mma.h>
#include <math.h>

using namespace nvcuda;

#define SEQ   4096
#define BATCH 8
#define MD    4
#define ORDER 256
#define INPUT 256
#define HID   512
#define MSZ   1280
#define NH    4096      // complex FFT size (= 8192/2), real-FFT packing
#define LOGH  12
#define KS    4160      // spectrum row stride: 4096 bitrev slots + nyquist + pad
#define FFT_T 512

typedef wmma::fragment<wmma::matrix_a, 16, 16, 8, wmma::precision::tf32, wmma::row_major> FragA;
typedef wmma::fragment<wmma::matrix_b, 16, 16, 8, wmma::precision::tf32, wmma::row_major> FragBr;
typedef wmma::fragment<wmma::matrix_b, 16, 16, 8, wmma::precision::tf32, wmma::col_major> FragBc;
typedef wmma::fragment<wmma::accumulator, 16, 16, 8, float> FragC;

// ---------------- scratch (static device globals; zero-init, no allocation) ---
__device__ float  g_u  [32 * SEQ];
__device__ float2 g_tw [NH];            // e^{-2*pi*i*k/8192}, k = 0..4095
__device__ float  g_Ure[32 * KS];
__device__ float  g_Uim[32 * KS];
__device__ float  g_Hre[ORDER * KS];
__device__ float  g_Him[ORDER * KS];
__device__ float  g_Gre[HID * MD * KS];
__device__ float  g_Gim[HID * MD * KS];
__device__ float  g_hx [BATCH * HID * SEQ];  // x-part of h (pre-relu), [b][h][t]

__device__ __forceinline__ int rev12(int x) { return (int)(__brev((unsigned)x) >> 20); }

// split a float fragment into tf32 hi/lo for 3xTF32 error compensation
template <typename F>
__device__ __forceinline__ void split_tf32(F& hi, F& lo) {
    #pragma unroll
    for (int i = 0; i < hi.num_elements; ++i) {
        float v = hi.x[i];
        float h = wmma::__float_to_tf32(v);
        hi.x[i] = h;
        lo.x[i] = wmma::__float_to_tf32(v - h);
    }
}

// ---------------- twiddle table ------------------------------------------------
__global__ void twiddle_kernel() {
    int k = blockIdx.x * blockDim.x + threadIdx.x;
    if (k < NH) {
        float s, c;
        sincospif(-(float)k / 4096.0f, &s, &c);   // e^{-2 pi i k / 8192}
        g_tw[k] = make_float2(c, s);
    }
}

// ---------------- u = relu(x @ Wu^T + b) ----------------------------------------
__global__ void u_kernel(const float* __restrict__ x,
                         const float* __restrict__ Wu_w,
                         const float* __restrict__ Wu_b) {
    int gw   = (blockIdx.x * blockDim.x + threadIdx.x) >> 5;
    int lane = threadIdx.x & 31;
    if (gw >= BATCH * SEQ) return;
    int b = gw >> 12, t = gw & (SEQ - 1);
    const float* xp = x + (size_t)(b * SEQ + t) * INPUT;
    float a0 = 0.f, a1 = 0.f, a2 = 0.f, a3 = 0.f;
    #pragma unroll
    for (int i = lane; i < INPUT; i += 32) {
        float xv = xp[i];
        a0 = fmaf(xv, __ldg(&Wu_w[0 * INPUT + i]), a0);
        a1 = fmaf(xv, __ldg(&Wu_w[1 * INPUT + i]), a1);
        a2 = fmaf(xv, __ldg(&Wu_w[2 * INPUT + i]), a2);
        a3 = fmaf(xv, __ldg(&Wu_w[3 * INPUT + i]), a3);
    }
    #pragma unroll
    for (int off = 16; off; off >>= 1) {
        a0 += __shfl_down_sync(0xffffffffu, a0, off);
        a1 += __shfl_down_sync(0xffffffffu, a1, off);
        a2 += __shfl_down_sync(0xffffffffu, a2, off);
        a3 += __shfl_down_sync(0xffffffffu, a3, off);
    }
    if (lane == 0) {
        g_u[(b * 4 + 0) * SEQ + t] = fmaxf(a0 + Wu_b[0], 0.f);
        g_u[(b * 4 + 1) * SEQ + t] = fmaxf(a1 + Wu_b[1], 0.f);
        g_u[(b * 4 + 2) * SEQ + t] = fmaxf(a2 + Wu_b[2], 0.f);
        g_u[(b * 4 + 3) * SEQ + t] = fmaxf(a3 + Wu_b[3], 0.f);
    }
}

// ---------------- 4096-pt FFT cores (radix-2, shared memory) -------------------
__device__ __forceinline__ void dif12(float* sre, float* sim, int tid) {
    #pragma unroll
    for (int s = LOGH - 1; s >= 0; --s) {
        int m = 1 << s;
        #pragma unroll
        for (int r = 0; r < (NH / 2) / FFT_T; ++r) {
            int k  = tid + r * FFT_T;
            int j  = k & (m - 1);
            int i0 = ((k >> s) << (s + 1)) + j;
            int i1 = i0 + m;
            float2 w = g_tw[j << (LOGH - s)];
            float ar = sre[i0], ai = sim[i0];
            float br = sre[i1], bi = sim[i1];
            sre[i0] = ar + br;
            sim[i0] = ai + bi;
            float dr = ar - br, di = ai - bi;
            sre[i1] = dr * w.x - di * w.y;
            sim[i1] = dr * w.y + di * w.x;
        }
        __syncthreads();
    }
}

__device__ __forceinline__ void dit12_inv(float* sre, float* sim, int tid) {
    #pragma unroll
    for (int s = 0; s < LOGH; ++s) {
        int m = 1 << s;
        #pragma unroll
        for (int r = 0; r < (NH / 2) / FFT_T; ++r) {
            int k  = tid + r * FFT_T;
            int j  = k & (m - 1);
            int i0 = ((k >> s) << (s + 1)) + j;
            int i1 = i0 + m;
            float2 w = g_tw[j << (LOGH - s)];     // conj used below
            float br = sre[i1], bi = sim[i1];
            float vr = br * w.x + bi * w.y;
            float vi = bi * w.x - br * w.y;
            float ar = sre[i0], ai = sim[i0];
            sre[i0] = ar + vr;
            sim[i0] = ai + vi;
            sre[i1] = ar - vr;
            sim[i1] = ai - vi;
        }
        __syncthreads();
    }
}

// ---------------- forward real FFT (half spectrum, bit-reversed slots) ----------
__global__ void fft_fwd_kernel(const float* __restrict__ Hin, int mode) {
    __shared__ float sre[NH];
    __shared__ float sim[NH];
    int row = blockIdx.x;
    int tid = threadIdx.x;
    const float* in = mode ? (Hin + (size_t)row * SEQ) : (g_u + (size_t)row * SEQ);
    float* outre = mode ? (g_Hre + (size_t)row * KS) : (g_Ure + (size_t)row * KS);
    float* outim = mode ? (g_Him + (size_t)row * KS) : (g_Uim + (size_t)row * KS);

    const float2* in2 = (const float2*)in;
    #pragma unroll
    for (int r = 0; r < NH / FFT_T; ++r) {
        int n = tid + r * FFT_T;
        if (n < SEQ / 2) { float2 v = in2[n]; sre[n] = v.x; sim[n] = v.y; }
        else             { sre[n] = 0.f;      sim[n] = 0.f; }
    }
    __syncthreads();
    dif12(sre, sim, tid);

    #pragma unroll
    for (int r = 0; r < NH / FFT_T; ++r) {
        int j = tid + r * FFT_T;
        if (j == 0) {
            float zr = sre[0], zi = sim[0];
            outre[0]  = zr + zi;  outim[0]  = 0.f;
            outre[NH] = zr - zi;  outim[NH] = 0.f;
        } else {
            int k = rev12(j);
            int p = rev12(NH - k);
            float zjr = sre[j], zji = sim[j];
            float zpr = sre[p], zpi = sim[p];
            float Ar = 0.5f * (zjr + zpr), Ai = 0.5f * (zji - zpi);
            float Br = 0.5f * (zji + zpi), Bi = -0.5f * (zjr - zpr);
            float2 w = g_tw[k];
            outre[j] = Ar + w.x * Br - w.y * Bi;
            outim[j] = Ai + w.x * Bi + w.y * Br;
        }
    }
}

// ---------------- G[h,d,:] = sum_o Wh[h, d*256+o] * Hspec[o,:]  (3xTF32) --------
__global__ void gbuild_tf32_kernel(const float* __restrict__ Wh_w) {
    __shared__ float sA [64][36];
    __shared__ float sBr[32][68];
    __shared__ float sBi[32][68];
    int d  = blockIdx.z;
    int h0 = blockIdx.y * 64;
    int k0 = blockIdx.x * 64;
    int tid = threadIdx.x;
    int w  = tid >> 5;
    int wm = w >> 1, wn = w & 1;

    FragC accr[2], acci[2];
    #pragma unroll
    for (int j = 0; j < 2; ++j) { wmma::fill_fragment(accr[j], 0.f); wmma::fill_fragment(acci[j], 0.f); }

    for (int o0 = 0; o0 < ORDER; o0 += 32) {
        #pragma unroll
        for (int r = 0; r < 8; ++r) {
            int e = tid + r * 256;
            int m = e >> 5, kk = e & 31;
            sA[m][kk] = Wh_w[(size_t)(h0 + m) * MSZ + d * ORDER + o0 + kk];
        }
        #pragma unroll
        for (int r = 0; r < 8; ++r) {
            int e = tid + r * 256;
            int oo = e >> 6, nn = e & 63;
            size_t src = (size_t)(o0 + oo) * KS + k0 + nn;
            sBr[oo][nn] = g_Hre[src];
            sBi[oo][nn] = g_Him[src];
        }
        __syncthreads();
        #pragma unroll
        for (int kk8 = 0; kk8 < 32; kk8 += 8) {
            FragA ahi, alo;
            wmma::load_matrix_sync(ahi, &sA[wm * 16][kk8], 36);
            #pragma unroll
            for (int i = 0; i < ahi.num_elements; ++i) {
                float v = ahi.x[i];
                float hh = wmma::__float_to_tf32(v);
                ahi.x[i] = hh;
                alo.x[i] = wmma::__float_to_tf32(v - hh);
            }
            #pragma unroll
            for (int j = 0; j < 2; ++j) {
                FragBr bhi, blo;
                wmma::load_matrix_sync(bhi, &sBr[kk8][wn * 32 + j * 16], 68);
                split_tf32(bhi, blo);
                wmma::mma_sync(accr[j], ahi, bhi, accr[j]);
                wmma::mma_sync(accr[j], alo, bhi, accr[j]);
                wmma::mma_sync(accr[j], ahi, blo, accr[j]);
                wmma::load_matrix_sync(bhi, &sBi[kk8][wn * 32 + j * 16], 68);
                split_tf32(bhi, blo);
                wmma::mma_sync(acci[j], ahi, bhi, acci[j]);
                wmma::mma_sync(acci[j], alo, bhi, acci[j]);
                wmma::mma_sync(acci[j], ahi, blo, acci[j]);
            }
        }
        __syncthreads();
    }
    #pragma unroll
    for (int j = 0; j < 2; ++j) {
        size_t dst = ((size_t)(h0 + wm * 16) * MD + d) * KS + k0 + wn * 32 + j * 16;
        wmma::store_matrix_sync(&g_Gre[dst], accr[j], MD * KS, wmma::mem_row_major);
        wmma::store_matrix_sync(&g_Gim[dst], acci[j], MD * KS, wmma::mem_row_major);
    }
}

// ---------------- hx[b,h,t] = sum_i Wh[h,1024+i]*x[b,t,i] + Wh_b[h]  (3xTF32) ---
__global__ void hx_tf32_kernel(const float* __restrict__ x,
                               const float* __restrict__ Wh_w,
                               const float* __restrict__ Wh_b) {
    __shared__ float sA[64][36];
    __shared__ float sB[128][36];    // x tile [t][i] -> matrix_b col_major
    __shared__ float sBias[64][16];
    int b  = blockIdx.z;
    int h0 = blockIdx.y * 64;
    int t0 = blockIdx.x * 128;
    int tid = threadIdx.x;
    int w  = tid >> 5;
    int wm = w >> 1, wn = w & 1;

    #pragma unroll
    for (int r = 0; r < 4; ++r) {
        int e = tid + r * 256;
        sBias[e >> 4][e & 15] = Wh_b[h0 + (e >> 4)];
    }
    __syncthreads();

    FragC acc[4];
    #pragma unroll
    for (int j = 0; j < 4; ++j)
        wmma::load_matrix_sync(acc[j], &sBias[wm * 16][0], 16, wmma::mem_row_major);

    const float4* x4 = (const float4*)(x + (size_t)(b * SEQ + t0) * INPUT);
    for (int i0 = 0; i0 < INPUT; i0 += 32) {
        #pragma unroll
        for (int r = 0; r < 8; ++r) {
            int e = tid + r * 256;
            int m = e >> 5, kk = e & 31;
            sA[m][kk] = Wh_w[(size_t)(h0 + m) * MSZ + MD * ORDER + i0 + kk];
        }
        #pragma unroll
        for (int r = 0; r < 4; ++r) {
            int e = tid + r * 256;     // 1024 float4 loads
            int q = e & 7, tt = e >> 3;
            float4 v = x4[(size_t)tt * (INPUT / 4) + (i0 >> 2) + q];
            *(float4*)&sB[tt][q * 4] = v;
        }
        __syncthreads();
        #pragma unroll
        for (int kk8 = 0; kk8 < 32; kk8 += 8) {
            FragA ahi, alo;
            wmma::load_matrix_sync(ahi, &sA[wm * 16][kk8], 36);
            #pragma unroll
            for (int i = 0; i < ahi.num_elements; ++i) {
                float v = ahi.x[i];
                float hh = wmma::__float_to_tf32(v);
                ahi.x[i] = hh;
                alo.x[i] = wmma::__float_to_tf32(v - hh);
            }
            #pragma unroll
            for (int j = 0; j < 4; ++j) {
                FragBc bhi, blo;
                wmma::load_matrix_sync(bhi, &sB[wn * 64 + j * 16][kk8], 36);
                split_tf32(bhi, blo);
                wmma::mma_sync(acc[j], ahi, bhi, acc[j]);
                wmma::mma_sync(acc[j], alo, bhi, acc[j]);
                wmma::mma_sync(acc[j], ahi, blo, acc[j]);
            }
        }
        __syncthreads();
    }
    #pragma unroll
    for (int j = 0; j < 4; ++j) {
        size_t dst = ((size_t)b * HID + h0 + wm * 16) * SEQ + t0 + wn * 64 + j * 16;
        wmma::store_matrix_sync(&g_hx[dst], acc[j], SEQ, wmma::mem_row_major);
    }
}

// ---------------- P = sum_d G*U ; real-iFFT ; h = relu(m + hx) (in-place) -------
__global__ void pifft_kernel() {
    __shared__ float sre[NH];
    __shared__ float sim[NH];
    __shared__ float s_nyq;
    int h = blockIdx.x >> 3;
    int b = blockIdx.x & 7;
    int tid = threadIdx.x;

    const float* Ur = g_Ure + (size_t)b * MD * KS;
    const float* Ui = g_Uim + (size_t)b * MD * KS;
    const float* Gr = g_Gre + (size_t)h * MD * KS;
    const float* Gi = g_Gim + (size_t)h * MD * KS;

    #pragma unroll
    for (int r = 0; r < NH / FFT_T; ++r) {
        int j = tid + r * FFT_T;
        float pr = 0.f, pi = 0.f;
        #pragma unroll
        for (int d = 0; d < MD; ++d) {
            float ur = Ur[d * KS + j], ui = Ui[d * KS + j];
            float gr = Gr[d * KS + j], gi = Gi[d * KS + j];
            pr += ur * gr - ui * gi;
            pi += ur * gi + ui * gr;
        }
        sre[j] = pr;
        sim[j] = pi;
    }
    if (tid == 0) {
        float pn = 0.f;
        #pragma unroll
        for (int d = 0; d < MD; ++d)
            pn += Ur[d * KS + NH] * Gr[d * KS + NH] - Ui[d * KS + NH] * Gi[d * KS + NH];
        s_nyq = pn;
    }
    __syncthreads();

    float zr[NH / FFT_T], zi[NH / FFT_T];
    #pragma unroll
    for (int r = 0; r < NH / FFT_T; ++r) {
        int j = tid + r * FFT_T;
        if (j == 0) {
            float p0 = sre[0], pn = s_nyq;
            zr[r] = 0.5f * (p0 + pn);
            zi[r] = 0.5f * (p0 - pn);
        } else {
            int k = rev12(j);
            int p = rev12(NH - k);
            float pjr = sre[j], pji = sim[j];
            float ppr = sre[p], ppi = sim[p];
            float Xer = 0.5f * (pjr + ppr), Xei = 0.5f * (pji - ppi);
            float Dr  = 0.5f * (pjr - ppr), Di  = 0.5f * (pji + ppi);
            float2 w = g_tw[k];
            float Xor = w.x * Dr + w.y * Di;
            float Xoi = w.x * Di - w.y * Dr;
            zr[r] = Xer - Xoi;
            zi[r] = Xei + Xor;
        }
    }
    __syncthreads();
    #pragma unroll
    for (int r = 0; r < NH / FFT_T; ++r) {
        int j = tid + r * FFT_T;
        sre[j] = zr[r];
        sim[j] = zi[r];
    }
    __syncthreads();

    dit12_inv(sre, sim, tid);

    float* hxp = g_hx + (size_t)(b * HID + h) * SEQ;
    float2* hx2 = (float2*)hxp;
    const float inv_n = 1.0f / 4096.0f;
    #pragma unroll
    for (int r = 0; r < (SEQ / 2) / FFT_T; ++r) {
        int n = tid + r * FFT_T;
        float2 old = hx2[n];
        float2 v;
        v.x = fmaxf(fmaf(sre[n], inv_n, old.x), 0.f);
        v.y = fmaxf(fmaf(sim[n], inv_n, old.y), 0.f);
        hx2[n] = v;
    }
}

// ---------------- transpose [b][h][t] -> out [b][t][h] --------------------------
__global__ void transpose_kernel(float* __restrict__ out) {
    __shared__ float tile[32][33];
    int b  = blockIdx.z;
    int h0 = blockIdx.y * 32;
    int t0 = blockIdx.x * 32;
    int tx = threadIdx.x, ty = threadIdx.y;
    #pragma unroll
    for (int r = 0; r < 32; r += 8)
        tile[ty + r][tx] = g_hx[(size_t)(b * HID + h0 + ty + r) * SEQ + t0 + tx];
    __syncthreads();
    #pragma unroll
    for (int r = 0; r < 32; r += 8)
        out[(size_t)(b * SEQ + t0 + ty + r) * HID + h0 + tx] = tile[tx][ty + r];
}

// ---------------- h[:, -1, :] appended after h -----------------------------------
__global__ void last_kernel(float* __restrict__ out) {
    int i = blockIdx.x * blockDim.x + threadIdx.x;
    if (i < BATCH * HID)
        out[(size_t)BATCH * SEQ * HID + i] = g_hx[(size_t)i * SEQ + (SEQ - 1)];
}

// ---------------- launch ----------------------------------------------------------
extern "C" void kernel_launch(void* const* d_in, const int* in_sizes, int n_in,
                              void* d_out, int out_size) {
    const float* x    = (const float*)d_in[0];
    const float* Wu_w = (const float*)d_in[1];
    const float* Wu_b = (const float*)d_in[2];
    const float* Wh_w = (const float*)d_in[3];
    const float* Wh_b = (const float*)d_in[4];
    const float* H    = (const float*)d_in[5];
    float* out = (float*)d_out;

    twiddle_kernel<<<8, 512>>>();
    u_kernel<<<(BATCH * SEQ * 32) / 256, 256>>>(x, Wu_w, Wu_b);

    fft_fwd_kernel<<<32,    FFT_T>>>(nullptr, 0);   // u spectra (half, bitrev)
    fft_fwd_kernel<<<ORDER, FFT_T>>>(H, 1);         // H spectra (half, bitrev)

    gbuild_tf32_kernel<<<dim3(KS / 64, HID / 64, MD), 256>>>(Wh_w);
    hx_tf32_kernel<<<dim3(SEQ / 128, HID / 64, BATCH), 256>>>(x, Wh_w, Wh_b);

    pifft_kernel<<<HID * BATCH, FFT_T>>>();

    transpose_kernel<<<dim3(SEQ / 32, HID / 32, BATCH), dim3(32, 8)>>>(out);
    if (out_size >= BATCH * SEQ * HID + BATCH * HID)
        last_kernel<<<8, 512>>>(out);
}

// round 4
// speedup vs baseline: 1.6420x; 1.6420x over previous
#include <cuda_runtime.h>
#include <cuda_bf16.h>
#include <mma.h>
#include <math.h>

using namespace nvcuda;

#define SEQ   4096
#define BATCH 8
#define MD    4
#define ORDER 256
#define INPUT 256
#define HID   512
#define MSZ   1280
#define NH    4096      // complex FFT size (= 8192/2), real-FFT packing
#define LOGH  12
#define KS    4160      // spectrum row stride: 4096 bitrev slots + nyquist + pad
#define FFT_T 512

typedef wmma::fragment<wmma::matrix_a, 16, 16, 16, __nv_bfloat16, wmma::row_major> FA;
typedef wmma::fragment<wmma::matrix_b, 16, 16, 16, __nv_bfloat16, wmma::row_major> FBr;
typedef wmma::fragment<wmma::matrix_b, 16, 16, 16, __nv_bfloat16, wmma::col_major> FBc;
typedef wmma::fragment<wmma::accumulator, 16, 16, 16, float> FC;

// ---------------- scratch (static device globals; zero-init, no allocation) ---
__device__ float  g_u  [32 * SEQ];
__device__ float2 g_tw [NH];            // e^{-2*pi*i*k/8192}
__device__ float  g_Ure[32 * KS];
__device__ float  g_Uim[32 * KS];
__device__ float  g_Hre[ORDER * KS];
__device__ float  g_Him[ORDER * KS];
__device__ float  g_Gre[HID * MD * KS];
__device__ float  g_Gim[HID * MD * KS];
__device__ float  g_hx [BATCH * HID * SEQ];  // x-part of h (pre-relu), [b][h][t]

__device__ __forceinline__ int rev12(int x) { return (int)(__brev((unsigned)x) >> 20); }

__device__ __forceinline__ void bsplit(float v, __nv_bfloat16& hi, __nv_bfloat16& lo) {
    hi = __float2bfloat16(v);
    lo = __float2bfloat16(v - __bfloat162float(hi));
}

// ---------------- twiddle table ------------------------------------------------
__global__ void twiddle_kernel() {
    int k = blockIdx.x * blockDim.x + threadIdx.x;
    if (k < NH) {
        float s, c;
        sincospif(-(float)k / 4096.0f, &s, &c);
        g_tw[k] = make_float2(c, s);
    }
}

// ---------------- u = relu(x @ Wu^T + b) ----------------------------------------
__global__ void u_kernel(const float* __restrict__ x,
                         const float* __restrict__ Wu_w,
                         const float* __restrict__ Wu_b) {
    int gw   = (blockIdx.x * blockDim.x + threadIdx.x) >> 5;
    int lane = threadIdx.x & 31;
    if (gw >= BATCH * SEQ) return;
    int b = gw >> 12, t = gw & (SEQ - 1);
    const float* xp = x + (size_t)(b * SEQ + t) * INPUT;
    float a0 = 0.f, a1 = 0.f, a2 = 0.f, a3 = 0.f;
    #pragma unroll
    for (int i = lane; i < INPUT; i += 32) {
        float xv = xp[i];
        a0 = fmaf(xv, __ldg(&Wu_w[0 * INPUT + i]), a0);
        a1 = fmaf(xv, __ldg(&Wu_w[1 * INPUT + i]), a1);
        a2 = fmaf(xv, __ldg(&Wu_w[2 * INPUT + i]), a2);
        a3 = fmaf(xv, __ldg(&Wu_w[3 * INPUT + i]), a3);
    }
    #pragma unroll
    for (int off = 16; off; off >>= 1) {
        a0 += __shfl_down_sync(0xffffffffu, a0, off);
        a1 += __shfl_down_sync(0xffffffffu, a1, off);
        a2 += __shfl_down_sync(0xffffffffu, a2, off);
        a3 += __shfl_down_sync(0xffffffffu, a3, off);
    }
    if (lane == 0) {
        g_u[(b * 4 + 0) * SEQ + t] = fmaxf(a0 + Wu_b[0], 0.f);
        g_u[(b * 4 + 1) * SEQ + t] = fmaxf(a1 + Wu_b[1], 0.f);
        g_u[(b * 4 + 2) * SEQ + t] = fmaxf(a2 + Wu_b[2], 0.f);
        g_u[(b * 4 + 3) * SEQ + t] = fmaxf(a3 + Wu_b[3], 0.f);
    }
}

// ---------------- 4096-pt FFT cores (radix-2, shared memory) -------------------
__device__ __forceinline__ void dif12(float* sre, float* sim, int tid) {
    #pragma unroll
    for (int s = LOGH - 1; s >= 0; --s) {
        int m = 1 << s;
        #pragma unroll
        for (int r = 0; r < (NH / 2) / FFT_T; ++r) {
            int k  = tid + r * FFT_T;
            int j  = k & (m - 1);
            int i0 = ((k >> s) << (s + 1)) + j;
            int i1 = i0 + m;
            float2 w = g_tw[j << (LOGH - s)];
            float ar = sre[i0], ai = sim[i0];
            float br = sre[i1], bi = sim[i1];
            sre[i0] = ar + br;
            sim[i0] = ai + bi;
            float dr = ar - br, di = ai - bi;
            sre[i1] = dr * w.x - di * w.y;
            sim[i1] = dr * w.y + di * w.x;
        }
        __syncthreads();
    }
}

// ---------------- forward real FFT (half spectrum, bit-reversed slots) ----------
__global__ void fft_fwd_kernel(const float* __restrict__ Hin, int mode) {
    __shared__ float sre[NH];
    __shared__ float sim[NH];
    int row = blockIdx.x;
    int tid = threadIdx.x;
    const float* in = mode ? (Hin + (size_t)row * SEQ) : (g_u + (size_t)row * SEQ);
    float* outre = mode ? (g_Hre + (size_t)row * KS) : (g_Ure + (size_t)row * KS);
    float* outim = mode ? (g_Him + (size_t)row * KS) : (g_Uim + (size_t)row * KS);

    const float2* in2 = (const float2*)in;
    #pragma unroll
    for (int r = 0; r < NH / FFT_T; ++r) {
        int n = tid + r * FFT_T;
        if (n < SEQ / 2) { float2 v = in2[n]; sre[n] = v.x; sim[n] = v.y; }
        else             { sre[n] = 0.f;      sim[n] = 0.f; }
    }
    __syncthreads();
    dif12(sre, sim, tid);

    #pragma unroll
    for (int r = 0; r < NH / FFT_T; ++r) {
        int j = tid + r * FFT_T;
        if (j == 0) {
            float zr = sre[0], zi = sim[0];
            outre[0]  = zr + zi;  outim[0]  = 0.f;
            outre[NH] = zr - zi;  outim[NH] = 0.f;
        } else {
            int k = rev12(j);
            int p = rev12(NH - k);
            float zjr = sre[j], zji = sim[j];
            float zpr = sre[p], zpi = sim[p];
            float Ar = 0.5f * (zjr + zpr), Ai = 0.5f * (zji - zpi);
            float Br = 0.5f * (zji + zpi), Bi = -0.5f * (zjr - zpr);
            float2 w = g_tw[k];
            outre[j] = Ar + w.x * Br - w.y * Bi;
            outim[j] = Ai + w.x * Bi + w.y * Br;
        }
    }
}

// ---------------- G[h,d,:] = sum_o Wh[h, d*256+o] * Hspec[o,:]  (bf16 split) ----
__global__ __launch_bounds__(256)
void gbuild_bf16_kernel(const float* __restrict__ Wh_w) {
    __shared__ __nv_bfloat16 sAhi[64][40], sAlo[64][40];        // [m][k]
    __shared__ __nv_bfloat16 sBhi[2][32][72], sBlo[2][32][72];  // [re/im][k][n]
    int d  = blockIdx.z;
    int h0 = blockIdx.y * 64;
    int k0 = blockIdx.x * 64;
    int tid = threadIdx.x;
    int w  = tid >> 5;
    int wm = w & 3;      // m tile
    int wn = w >> 2;     // n half (32 cols)

    FC accr[2], acci[2];
    #pragma unroll
    for (int j = 0; j < 2; ++j) { wmma::fill_fragment(accr[j], 0.f); wmma::fill_fragment(acci[j], 0.f); }

    for (int o0 = 0; o0 < ORDER; o0 += 32) {
        #pragma unroll
        for (int r = 0; r < 8; ++r) {
            int e = tid + r * 256;
            int m = e >> 5, kk = e & 31;
            float v = Wh_w[(size_t)(h0 + m) * MSZ + d * ORDER + o0 + kk];
            bsplit(v, sAhi[m][kk], sAlo[m][kk]);
        }
        #pragma unroll
        for (int r = 0; r < 8; ++r) {
            int e = tid + r * 256;
            int oo = e >> 6, nn = e & 63;
            size_t src = (size_t)(o0 + oo) * KS + k0 + nn;
            bsplit(g_Hre[src], sBhi[0][oo][nn], sBlo[0][oo][nn]);
            bsplit(g_Him[src], sBhi[1][oo][nn], sBlo[1][oo][nn]);
        }
        __syncthreads();
        #pragma unroll
        for (int kk = 0; kk < 32; kk += 16) {
            FA ahi, alo;
            wmma::load_matrix_sync(ahi, &sAhi[wm * 16][kk], 40);
            wmma::load_matrix_sync(alo, &sAlo[wm * 16][kk], 40);
            #pragma unroll
            for (int j = 0; j < 2; ++j) {
                FBr bhi, blo;
                wmma::load_matrix_sync(bhi, &sBhi[0][kk][wn * 32 + j * 16], 72);
                wmma::load_matrix_sync(blo, &sBlo[0][kk][wn * 32 + j * 16], 72);
                wmma::mma_sync(accr[j], ahi, bhi, accr[j]);
                wmma::mma_sync(accr[j], alo, bhi, accr[j]);
                wmma::mma_sync(accr[j], ahi, blo, accr[j]);
                wmma::load_matrix_sync(bhi, &sBhi[1][kk][wn * 32 + j * 16], 72);
                wmma::load_matrix_sync(blo, &sBlo[1][kk][wn * 32 + j * 16], 72);
                wmma::mma_sync(acci[j], ahi, bhi, acci[j]);
                wmma::mma_sync(acci[j], alo, bhi, acci[j]);
                wmma::mma_sync(acci[j], ahi, blo, acci[j]);
            }
        }
        __syncthreads();
    }
    #pragma unroll
    for (int j = 0; j < 2; ++j) {
        size_t dst = ((size_t)(h0 + wm * 16) * MD + d) * KS + k0 + wn * 32 + j * 16;
        wmma::store_matrix_sync(&g_Gre[dst], accr[j], MD * KS, wmma::mem_row_major);
        wmma::store_matrix_sync(&g_Gim[dst], acci[j], MD * KS, wmma::mem_row_major);
    }
}

// ---------------- hx[b,h,t] = sum_i Wh[h,1024+i]*x[b,t,i] + Wh_b[h]  (bf16) -----
__global__ __launch_bounds__(256)
void hx_bf16_kernel(const float* __restrict__ x,
                    const float* __restrict__ Wh_w,
                    const float* __restrict__ Wh_b) {
    __shared__ __nv_bfloat16 sAhi[64][40], sAlo[64][40];    // [h][i]
    __shared__ __nv_bfloat16 sBhi[128][40], sBlo[128][40];  // [t][i]
    __shared__ float sBias[64][16];
    int b  = blockIdx.z;
    int h0 = blockIdx.y * 64;
    int t0 = blockIdx.x * 128;
    int tid = threadIdx.x;
    int w  = tid >> 5;
    int wm = w & 3;     // m tile
    int wn = w >> 2;    // t half (64 cols)

    #pragma unroll
    for (int r = 0; r < 4; ++r) {
        int e = tid + r * 256;
        sBias[e >> 4][e & 15] = Wh_b[h0 + (e >> 4)];
    }
    __syncthreads();

    FC acc[4];
    #pragma unroll
    for (int j = 0; j < 4; ++j)
        wmma::load_matrix_sync(acc[j], &sBias[wm * 16][0], 16, wmma::mem_row_major);

    const float4* x4 = (const float4*)(x + (size_t)(b * SEQ + t0) * INPUT);
    for (int i0 = 0; i0 < INPUT; i0 += 32) {
        #pragma unroll
        for (int r = 0; r < 8; ++r) {
            int e = tid + r * 256;
            int m = e >> 5, kk = e & 31;
            float v = Wh_w[(size_t)(h0 + m) * MSZ + MD * ORDER + i0 + kk];
            bsplit(v, sAhi[m][kk], sAlo[m][kk]);
        }
        #pragma unroll
        for (int r = 0; r < 4; ++r) {
            int e = tid + r * 256;
            int tt = e >> 3, q = e & 7;
            float4 v = x4[(size_t)tt * (INPUT / 4) + (i0 >> 2) + q];
            bsplit(v.x, sBhi[tt][q * 4 + 0], sBlo[tt][q * 4 + 0]);
            bsplit(v.y, sBhi[tt][q * 4 + 1], sBlo[tt][q * 4 + 1]);
            bsplit(v.z, sBhi[tt][q * 4 + 2], sBlo[tt][q * 4 + 2]);
            bsplit(v.w, sBhi[tt][q * 4 + 3], sBlo[tt][q * 4 + 3]);
        }
        __syncthreads();
        #pragma unroll
        for (int kk = 0; kk < 32; kk += 16) {
            FA ahi, alo;
            wmma::load_matrix_sync(ahi, &sAhi[wm * 16][kk], 40);
            wmma::load_matrix_sync(alo, &sAlo[wm * 16][kk], 40);
            #pragma unroll
            for (int j = 0; j < 4; ++j) {
                FBc bhi, blo;
                wmma::load_matrix_sync(bhi, &sBhi[wn * 64 + j * 16][kk], 40);
                wmma::load_matrix_sync(blo, &sBlo[wn * 64 + j * 16][kk], 40);
                wmma::mma_sync(acc[j], ahi, bhi, acc[j]);
                wmma::mma_sync(acc[j], alo, bhi, acc[j]);
                wmma::mma_sync(acc[j], ahi, blo, acc[j]);
            }
        }
        __syncthreads();
    }
    #pragma unroll
    for (int j = 0; j < 4; ++j) {
        size_t dst = ((size_t)b * HID + h0 + wm * 16) * SEQ + t0 + wn * 64 + j * 16;
        wmma::store_matrix_sync(&g_hx[dst], acc[j], SEQ, wmma::mem_row_major);
    }
}

// ---------------- P = sum_d G*U ; real-iFFT (2 batches/block) -------------------
__global__ __launch_bounds__(FFT_T)
void pifft_kernel() {
    __shared__ float sre[2][NH];
    __shared__ float sim[2][NH];
    __shared__ float s_nyq[2];
    int h  = blockIdx.x >> 2;
    int bp = blockIdx.x & 3;
    int b0 = bp * 2;
    int tid = threadIdx.x;

    const float* Ur0 = g_Ure + (size_t)b0 * MD * KS;
    const float* Ui0 = g_Uim + (size_t)b0 * MD * KS;
    const float* Ur1 = Ur0 + MD * KS;
    const float* Ui1 = Ui0 + MD * KS;
    const float* Gr  = g_Gre + (size_t)h * MD * KS;
    const float* Gi  = g_Gim + (size_t)h * MD * KS;

    // pointwise product (bit-reversed slot order), both batches
    #pragma unroll
    for (int r = 0; r < NH / FFT_T; ++r) {
        int j = tid + r * FFT_T;
        float pr0 = 0.f, pi0 = 0.f, pr1 = 0.f, pi1 = 0.f;
        #pragma unroll
        for (int d = 0; d < MD; ++d) {
            float gr = Gr[d * KS + j], gi = Gi[d * KS + j];
            float ur = Ur0[d * KS + j], ui = Ui0[d * KS + j];
            pr0 += ur * gr - ui * gi;
            pi0 += ur * gi + ui * gr;
            ur = Ur1[d * KS + j]; ui = Ui1[d * KS + j];
            pr1 += ur * gr - ui * gi;
            pi1 += ur * gi + ui * gr;
        }
        sre[0][j] = pr0; sim[0][j] = pi0;
        sre[1][j] = pr1; sim[1][j] = pi1;
    }
    if (tid < 2) {
        const float* Urb = tid ? Ur1 : Ur0;
        const float* Uib = tid ? Ui1 : Ui0;
        float pn = 0.f;
        #pragma unroll
        for (int d = 0; d < MD; ++d)
            pn += Urb[d * KS + NH] * Gr[d * KS + NH] - Uib[d * KS + NH] * Gi[d * KS + NH];
        s_nyq[tid] = pn;
    }
    __syncthreads();

    // inverse pack (both batches)
    float zr[2][NH / FFT_T], zi[2][NH / FFT_T];
    #pragma unroll
    for (int r = 0; r < NH / FFT_T; ++r) {
        int j = tid + r * FFT_T;
        if (j == 0) {
            #pragma unroll
            for (int q = 0; q < 2; ++q) {
                float p0 = sre[q][0], pn = s_nyq[q];
                zr[q][r] = 0.5f * (p0 + pn);
                zi[q][r] = 0.5f * (p0 - pn);
            }
        } else {
            int k = rev12(j);
            int p = rev12(NH - k);
            float2 w = g_tw[k];
            #pragma unroll
            for (int q = 0; q < 2; ++q) {
                float pjr = sre[q][j], pji = sim[q][j];
                float ppr = sre[q][p], ppi = sim[q][p];
                float Xer = 0.5f * (pjr + ppr), Xei = 0.5f * (pji - ppi);
                float Dr  = 0.5f * (pjr - ppr), Di  = 0.5f * (pji + ppi);
                float Xor = w.x * Dr + w.y * Di;
                float Xoi = w.x * Di - w.y * Dr;
                zr[q][r] = Xer - Xoi;
                zi[q][r] = Xei + Xor;
            }
        }
    }
    __syncthreads();
    #pragma unroll
    for (int r = 0; r < NH / FFT_T; ++r) {
        int j = tid + r * FFT_T;
        sre[0][j] = zr[0][r]; sim[0][j] = zi[0][r];
        sre[1][j] = zr[1][r]; sim[1][j] = zi[1][r];
    }
    __syncthreads();

    // fused dual inverse DIT
    #pragma unroll
    for (int s = 0; s < LOGH; ++s) {
        int m = 1 << s;
        #pragma unroll
        for (int r = 0; r < (NH / 2) / FFT_T; ++r) {
            int k  = tid + r * FFT_T;
            int j  = k & (m - 1);
            int i0 = ((k >> s) << (s + 1)) + j;
            int i1 = i0 + m;
            float2 w = g_tw[j << (LOGH - s)];
            #pragma unroll
            for (int q = 0; q < 2; ++q) {
                float br = sre[q][i1], bi = sim[q][i1];
                float vr = br * w.x + bi * w.y;
                float vi = bi * w.x - br * w.y;
                float ar = sre[q][i0], ai = sim[q][i0];
                sre[q][i0] = ar + vr;
                sim[q][i0] = ai + vi;
                sre[q][i1] = ar - vr;
                sim[q][i1] = ai - vi;
            }
        }
        __syncthreads();
    }

    const float inv_n = 1.0f / 4096.0f;
    #pragma unroll
    for (int q = 0; q < 2; ++q) {
        float2* hx2 = (float2*)(g_hx + (size_t)((b0 + q) * HID + h) * SEQ);
        #pragma unroll
        for (int r = 0; r < (SEQ / 2) / FFT_T; ++r) {
            int n = tid + r * FFT_T;
            float2 old = hx2[n];
            float2 v;
            v.x = fmaxf(fmaf(sre[q][n], inv_n, old.x), 0.f);
            v.y = fmaxf(fmaf(sim[q][n], inv_n, old.y), 0.f);
            hx2[n] = v;
        }
    }
}

// ---------------- transpose [b][h][t] -> out [b][t][h] --------------------------
__global__ void transpose_kernel(float* __restrict__ out) {
    __shared__ float tile[32][33];
    int b  = blockIdx.z;
    int h0 = blockIdx.y * 32;
    int t0 = blockIdx.x * 32;
    int tx = threadIdx.x, ty = threadIdx.y;
    #pragma unroll
    for (int r = 0; r < 32; r += 8)
        tile[ty + r][tx] = g_hx[(size_t)(b * HID + h0 + ty + r) * SEQ + t0 + tx];
    __syncthreads();
    #pragma unroll
    for (int r = 0; r < 32; r += 8)
        out[(size_t)(b * SEQ + t0 + ty + r) * HID + h0 + tx] = tile[tx][ty + r];
}

// ---------------- h[:, -1, :] appended after h -----------------------------------
__global__ void last_kernel(float* __restrict__ out) {
    int i = blockIdx.x * blockDim.x + threadIdx.x;
    if (i < BATCH * HID)
        out[(size_t)BATCH * SEQ * HID + i] = g_hx[(size_t)i * SEQ + (SEQ - 1)];
}

// ---------------- launch ----------------------------------------------------------
extern "C" void kernel_launch(void* const* d_in, const int* in_sizes, int n_in,
                              void* d_out, int out_size) {
    const float* x    = (const float*)d_in[0];
    const float* Wu_w = (const float*)d_in[1];
    const float* Wu_b = (const float*)d_in[2];
    const float* Wh_w = (const float*)d_in[3];
    const float* Wh_b = (const float*)d_in[4];
    const float* H    = (const float*)d_in[5];
    float* out = (float*)d_out;

    twiddle_kernel<<<8, 512>>>();
    u_kernel<<<(BATCH * SEQ * 32) / 256, 256>>>(x, Wu_w, Wu_b);

    fft_fwd_kernel<<<32,    FFT_T>>>(nullptr, 0);   // u spectra (half, bitrev)
    fft_fwd_kernel<<<ORDER, FFT_T>>>(H, 1);         // H spectra (half, bitrev)

    gbuild_bf16_kernel<<<dim3(KS / 64, HID / 64, MD), 256>>>(Wh_w);
    hx_bf16_kernel<<<dim3(SEQ / 128, HID / 64, BATCH), 256>>>(x, Wh_w, Wh_b);

    pifft_kernel<<<HID * BATCH / 2, FFT_T>>>();

    transpose_kernel<<<dim3(SEQ / 32, HID / 32, BATCH), dim3(32, 8)>>>(out);
    if (out_size >= BATCH * SEQ * HID + BATCH * HID)
        last_kernel<<<8, 512>>>(out);
}